// round 4
// baseline (speedup 1.0000x reference)
#include <cuda_runtime.h>
#include <math.h>

// Problem constants (fixed shapes from setup_inputs)
#define T_TOK 8192          // B*S
#define Dm    512           // model dim
#define Fm    2048          // ffn dim
#define Em    64            // experts
#define Hh    4             // hash heads
#define NC    256           // Hh * Em routing columns
#define CAP   1024          // CAP_FACTOR*T*k/E

// GEMM tiling
#define BM 128
#define BN 128
#define BK 8

// Device-global scratch (allocation-free rule: static device arrays)
__device__ float g_logits[T_TOK * NC];                 // 8.4 MB
__device__ int   g_sel[T_TOK * 2];
__device__ int   g_count[Em];
__device__ int   g_toklist[Em * CAP];                  // slot ids (t*2+j)
__device__ float g_hbuf[(size_t)T_TOK * 2 * Fm];       // 134 MB hidden activations

__device__ __forceinline__ float gelu_exact(float v) {
    return 0.5f * v * (1.0f + erff(v * 0.7071067811865475f));
}

// ---------------------------------------------------------------------------
// K0: zero output + expert counters
// ---------------------------------------------------------------------------
__global__ void zero_kernel(float* __restrict__ out) {
    int i = blockIdx.x * 256 + threadIdx.x;
    if (i < T_TOK * Dm) out[i] = 0.0f;
    if (i < Em) g_count[i] = 0;
}

// ---------------------------------------------------------------------------
// K1: routing logits GEMM  logits[t, h*64+e] = sum_d x[t,d] * hp[h,d,e]
// fp32 128x128x8 tile, 8x8 per thread
// ---------------------------------------------------------------------------
__global__ __launch_bounds__(256, 2)
void route_gemm(const float* __restrict__ x, const float* __restrict__ hp) {
    __shared__ float As[BK][BM + 4];
    __shared__ float Bs[BK][BN];
    const int tid = threadIdx.x;
    const int bm = blockIdx.y * BM;
    const int bn = blockIdx.x * BN;
    const int arow = tid >> 1, akq = (tid & 1) << 2;
    const int bkr = tid >> 5, bnq = (tid & 31) << 2;
    const int tx = tid & 15, ty = tid >> 4;

    const int c = bn + bnq;                       // routing column = h*64 + e
    const float* bsrc = hp + (c >> 6) * (Dm * Em) + bkr * Em + (c & 63);
    const float* asrc = x + (size_t)(bm + arow) * Dm + akq;

    float acc[8][8];
#pragma unroll
    for (int i = 0; i < 8; i++)
#pragma unroll
        for (int j = 0; j < 8; j++) acc[i][j] = 0.0f;

    for (int k0 = 0; k0 < Dm; k0 += BK) {
        float4 av = *(const float4*)(asrc + k0);
        float4 bv = *(const float4*)(bsrc + (size_t)k0 * Em);
        As[akq + 0][arow] = av.x;
        As[akq + 1][arow] = av.y;
        As[akq + 2][arow] = av.z;
        As[akq + 3][arow] = av.w;
        *(float4*)&Bs[bkr][bnq] = bv;
        __syncthreads();
        float ar[8], br[8];
#pragma unroll
        for (int k = 0; k < BK; k++) {
            *(float4*)&ar[0] = *(const float4*)&As[k][ty * 4];
            *(float4*)&ar[4] = *(const float4*)&As[k][64 + ty * 4];
            *(float4*)&br[0] = *(const float4*)&Bs[k][tx * 4];
            *(float4*)&br[4] = *(const float4*)&Bs[k][64 + tx * 4];
#pragma unroll
            for (int i = 0; i < 8; i++)
#pragma unroll
                for (int j = 0; j < 8; j++)
                    acc[i][j] = fmaf(ar[i], br[j], acc[i][j]);
        }
        __syncthreads();
    }
#pragma unroll
    for (int i = 0; i < 8; i++) {
        int m = bm + ((i < 4) ? (ty * 4 + i) : (64 + ty * 4 + i - 4));
        float* dst = g_logits + (size_t)m * NC + bn;
        *(float4*)(dst + tx * 4)      = make_float4(acc[i][0], acc[i][1], acc[i][2], acc[i][3]);
        *(float4*)(dst + 64 + tx * 4) = make_float4(acc[i][4], acc[i][5], acc[i][6], acc[i][7]);
    }
}

// ---------------------------------------------------------------------------
// K2: per-token argmax per head (first index on tie), then stable top-2 over
// the H head scores (matches jax.lax.top_k tie-breaking).
// One warp per token.
// ---------------------------------------------------------------------------
__global__ void route_top2() {
    int t = (blockIdx.x * blockDim.x + threadIdx.x) >> 5;
    int lane = threadIdx.x & 31;
    if (t >= T_TOK) return;
    const float* lg = g_logits + (size_t)t * NC;
    float sc[Hh]; int cd[Hh];
#pragma unroll
    for (int h = 0; h < Hh; h++) {
        float v0 = lg[h * 64 + lane];
        float v1 = lg[h * 64 + 32 + lane];
        float v = v0; int idx = lane;
        if (v1 > v) { v = v1; idx = lane + 32; }
#pragma unroll
        for (int off = 16; off > 0; off >>= 1) {
            float ov = __shfl_xor_sync(0xffffffffu, v, off);
            int   oi = __shfl_xor_sync(0xffffffffu, idx, off);
            if (ov > v || (ov == v && oi < idx)) { v = ov; idx = oi; }
        }
        sc[h] = v; cd[h] = idx;      // idx == expert id (argmax over E)
    }
    if (lane == 0) {
        int h1 = 0;
#pragma unroll
        for (int h = 1; h < Hh; h++) if (sc[h] > sc[h1]) h1 = h;
        int h2 = -1;
#pragma unroll
        for (int h = 0; h < Hh; h++) {
            if (h == h1) continue;
            if (h2 < 0 || sc[h] > sc[h2]) h2 = h;
        }
        g_sel[t * 2 + 0] = cd[h1];
        g_sel[t * 2 + 1] = cd[h2];
    }
}

// ---------------------------------------------------------------------------
// K3: dispatch — per-expert slot lists via atomic counters.
// Position order differs from the reference cumsum, but with zero capacity
// drops (loads ~256 << C=1024) the result is permutation-invariant.
// ---------------------------------------------------------------------------
__global__ void dispatch_kernel() {
    int s = blockIdx.x * 256 + threadIdx.x;
    if (s >= T_TOK * 2) return;
    int e = g_sel[s];
    int p = atomicAdd(&g_count[e], 1);
    if (p < CAP) g_toklist[e * CAP + p] = s;
}

// ---------------------------------------------------------------------------
// K4: layer-1 grouped GEMM + exact GELU:  h[slot,:] = gelu(x[t,:] @ W1[e])
// grid: (Fm/BN, CAP/BM, Em); blocks past the expert's row count exit.
// ---------------------------------------------------------------------------
__global__ __launch_bounds__(256, 2)
void ffn1_kernel(const float* __restrict__ x, const float* __restrict__ W1) {
    const int e = blockIdx.z;
    const int n_e = min(g_count[e], CAP);
    const int m0b = blockIdx.y * BM;
    if (m0b >= n_e) return;
    const int bn = blockIdx.x * BN;

    __shared__ float As[BK][BM + 4];
    __shared__ float Bs[BK][BN];
    __shared__ int   stok[BM];
    const int tid = threadIdx.x;
    if (tid < BM) {
        int r = m0b + tid;
        stok[tid] = (r < n_e) ? g_toklist[e * CAP + r] : 0;
    }
    __syncthreads();

    const int arow = tid >> 1, akq = (tid & 1) << 2;
    const int bkr = tid >> 5, bnq = (tid & 31) << 2;
    const int tx = tid & 15, ty = tid >> 4;

    const float* asrc = x + (size_t)(stok[arow] >> 1) * Dm + akq;
    const float* bsrc = W1 + (size_t)e * Dm * Fm + (size_t)bkr * Fm + bn + bnq;

    float acc[8][8];
#pragma unroll
    for (int i = 0; i < 8; i++)
#pragma unroll
        for (int j = 0; j < 8; j++) acc[i][j] = 0.0f;

    for (int k0 = 0; k0 < Dm; k0 += BK) {
        float4 av = *(const float4*)(asrc + k0);
        float4 bv = *(const float4*)(bsrc + (size_t)k0 * Fm);
        As[akq + 0][arow] = av.x;
        As[akq + 1][arow] = av.y;
        As[akq + 2][arow] = av.z;
        As[akq + 3][arow] = av.w;
        *(float4*)&Bs[bkr][bnq] = bv;
        __syncthreads();
        float ar[8], br[8];
#pragma unroll
        for (int k = 0; k < BK; k++) {
            *(float4*)&ar[0] = *(const float4*)&As[k][ty * 4];
            *(float4*)&ar[4] = *(const float4*)&As[k][64 + ty * 4];
            *(float4*)&br[0] = *(const float4*)&Bs[k][tx * 4];
            *(float4*)&br[4] = *(const float4*)&Bs[k][64 + tx * 4];
#pragma unroll
            for (int i = 0; i < 8; i++)
#pragma unroll
                for (int j = 0; j < 8; j++)
                    acc[i][j] = fmaf(ar[i], br[j], acc[i][j]);
        }
        __syncthreads();
    }

#pragma unroll
    for (int i = 0; i < 8; i++) {
        int ml = (i < 4) ? (ty * 4 + i) : (64 + ty * 4 + i - 4);
        if (m0b + ml < n_e) {
            int slot = stok[ml];
            float* dst = g_hbuf + (size_t)slot * Fm + bn;
            *(float4*)(dst + tx * 4) = make_float4(
                gelu_exact(acc[i][0]), gelu_exact(acc[i][1]),
                gelu_exact(acc[i][2]), gelu_exact(acc[i][3]));
            *(float4*)(dst + 64 + tx * 4) = make_float4(
                gelu_exact(acc[i][4]), gelu_exact(acc[i][5]),
                gelu_exact(acc[i][6]), gelu_exact(acc[i][7]));
        }
    }
}

// ---------------------------------------------------------------------------
// K5: layer-2 grouped GEMM + scatter-mean:  out[t,:] += 0.5 * h[slot,:] @ W2[e]
// ---------------------------------------------------------------------------
__global__ __launch_bounds__(256, 2)
void ffn2_kernel(const float* __restrict__ W2, float* __restrict__ out) {
    const int e = blockIdx.z;
    const int n_e = min(g_count[e], CAP);
    const int m0b = blockIdx.y * BM;
    if (m0b >= n_e) return;
    const int bn = blockIdx.x * BN;

    __shared__ float As[BK][BM + 4];
    __shared__ float Bs[BK][BN];
    __shared__ int   stok[BM];
    const int tid = threadIdx.x;
    if (tid < BM) {
        int r = m0b + tid;
        stok[tid] = (r < n_e) ? g_toklist[e * CAP + r] : 0;
    }
    __syncthreads();

    const int arow = tid >> 1, akq = (tid & 1) << 2;
    const int bkr = tid >> 5, bnq = (tid & 31) << 2;
    const int tx = tid & 15, ty = tid >> 4;

    const float* asrc = g_hbuf + (size_t)stok[arow] * Fm + akq;
    const float* bsrc = W2 + (size_t)e * Fm * Dm + (size_t)bkr * Dm + bn + bnq;

    float acc[8][8];
#pragma unroll
    for (int i = 0; i < 8; i++)
#pragma unroll
        for (int j = 0; j < 8; j++) acc[i][j] = 0.0f;

    for (int k0 = 0; k0 < Fm; k0 += BK) {
        float4 av = *(const float4*)(asrc + k0);
        float4 bv = *(const float4*)(bsrc + (size_t)k0 * Dm);
        As[akq + 0][arow] = av.x;
        As[akq + 1][arow] = av.y;
        As[akq + 2][arow] = av.z;
        As[akq + 3][arow] = av.w;
        *(float4*)&Bs[bkr][bnq] = bv;
        __syncthreads();
        float ar[8], br[8];
#pragma unroll
        for (int k = 0; k < BK; k++) {
            *(float4*)&ar[0] = *(const float4*)&As[k][ty * 4];
            *(float4*)&ar[4] = *(const float4*)&As[k][64 + ty * 4];
            *(float4*)&br[0] = *(const float4*)&Bs[k][tx * 4];
            *(float4*)&br[4] = *(const float4*)&Bs[k][64 + tx * 4];
#pragma unroll
            for (int i = 0; i < 8; i++)
#pragma unroll
                for (int j = 0; j < 8; j++)
                    acc[i][j] = fmaf(ar[i], br[j], acc[i][j]);
        }
        __syncthreads();
    }

#pragma unroll
    for (int i = 0; i < 8; i++) {
        int ml = (i < 4) ? (ty * 4 + i) : (64 + ty * 4 + i - 4);
        if (m0b + ml < n_e) {
            int t = stok[ml] >> 1;
            float* base = out + (size_t)t * Dm + bn;
#pragma unroll
            for (int j = 0; j < 8; j++) {
                int col = (j < 4) ? (tx * 4 + j) : (64 + tx * 4 + j - 4);
                atomicAdd(base + col, 0.5f * acc[i][j]);
            }
        }
    }
}

// ---------------------------------------------------------------------------
extern "C" void kernel_launch(void* const* d_in, const int* in_sizes, int n_in,
                              void* d_out, int out_size) {
    const float* x  = (const float*)d_in[0];   // hidden_states [4,2048,512]
    const float* hp = (const float*)d_in[1];   // hash_proj [4,512,64]
    const float* W1 = (const float*)d_in[2];   // [64,512,2048]
    const float* W2 = (const float*)d_in[3];   // [64,2048,512]
    float* out = (float*)d_out;                // [4,2048,512]

    zero_kernel<<<(T_TOK * Dm + 255) / 256, 256>>>(out);
    route_gemm<<<dim3(NC / BN, T_TOK / BM), 256>>>(x, hp);
    route_top2<<<(T_TOK * 32) / 256, 256>>>();
    dispatch_kernel<<<(T_TOK * 2 + 255) / 256, 256>>>();
    ffn1_kernel<<<dim3(Fm / BN, CAP / BM, Em), 256>>>(x, W1);
    ffn2_kernel<<<dim3(Dm / BN, CAP / BM, Em), 256>>>(W2, out);
}

// round 8
// speedup vs baseline: 1.8147x; 1.8147x over previous
#include <cuda_runtime.h>
#include <cuda_bf16.h>
#include <math.h>
#include <stdint.h>

// ---------------------------------------------------------------- constants
#define T_TOK 8192
#define Dm    512
#define Fm    2048
#define Em    64
#define Hh    4
#define NC    256
#define CAP   1024
#define NSLOT (T_TOK * 2)

// routing fp32 GEMM tiling
#define BM 128
#define BN 128
#define BK 8

// mma FFN tiling
#define KCH   32
#define SPAD  40     // A smem row stride (bf16 elems)
#define BNPAD 132    // B smem row stride (fp32 elems), 132 % 32 == 4 -> conflict-free

// ---------------------------------------------------------------- scratch (~176MB total, R3-proven scale)
__device__ __align__(256) float g_logits[(size_t)T_TOK * NC];
__device__ __align__(256) int   g_sel[NSLOT];
__device__ __align__(256) int   g_count[Em];
__device__ __align__(256) int   g_toklist[Em * CAP];
__device__ __align__(256) float g_hbuf[(size_t)NSLOT * Fm];
__device__ __align__(256) float g_ybuf[(size_t)NSLOT * Dm];

// ---------------------------------------------------------------- helpers
__device__ __forceinline__ float gelu_exact(float v) {
    return 0.5f * v * (1.0f + erff(v * 0.7071067811865475f));
}
__device__ __forceinline__ uint32_t pack_bf(unsigned short a, unsigned short b) {
    return (uint32_t)a | ((uint32_t)b << 16);
}
// split float4 -> 4 hi bf16 (uint2) + 4 lo bf16 (uint2)   [A-operand producer]
__device__ __forceinline__ void split4(float4 v, uint2& h, uint2& l) {
    float f[4] = {v.x, v.y, v.z, v.w};
    unsigned short hs[4], ls[4];
#pragma unroll
    for (int i = 0; i < 4; i++) {
        __nv_bfloat16 hb = __float2bfloat16(f[i]);
        float r = f[i] - __bfloat162float(hb);
        hs[i] = __bfloat16_as_ushort(hb);
        ls[i] = __bfloat16_as_ushort(__float2bfloat16(r));
    }
    h = make_uint2(pack_bf(hs[0], hs[1]), pack_bf(hs[2], hs[3]));
    l = make_uint2(pack_bf(ls[0], ls[1]), pack_bf(ls[2], ls[3]));
}
__device__ __forceinline__ void mma_bf16(float& d0, float& d1, float& d2, float& d3,
                                         uint32_t a0, uint32_t a1, uint32_t a2, uint32_t a3,
                                         uint32_t b0, uint32_t b1) {
    asm volatile(
        "mma.sync.aligned.m16n8k16.row.col.f32.bf16.bf16.f32 "
        "{%0,%1,%2,%3},{%4,%5,%6,%7},{%8,%9},{%0,%1,%2,%3};"
        : "+f"(d0), "+f"(d1), "+f"(d2), "+f"(d3)
        : "r"(a0), "r"(a1), "r"(a2), "r"(a3), "r"(b0), "r"(b1));
}
__device__ __forceinline__ uint32_t lds32(const __nv_bfloat16* base, int row, int col) {
    return *(const uint32_t*)((const char*)base + (row * SPAD + col) * 2);
}
// pack bf16(f0),bf16(f1) (round-nearest) into one reg: lo=f0, hi=f1
__device__ __forceinline__ uint32_t cvt2_bf16(float f0, float f1) {
    uint32_t d;
    asm("cvt.rn.bf16x2.f32 %0, %1, %2;" : "=r"(d) : "f"(f1), "f"(f0));
    return d;
}

// ---------------------------------------------------------------- K0: misc
__global__ void zc_kernel() {
    if (threadIdx.x < Em) g_count[threadIdx.x] = 0;
}

// ---------------------------------------------------------------- routing (proven in R3)
__global__ __launch_bounds__(256, 2)
void route_gemm(const float* __restrict__ x, const float* __restrict__ hp) {
    __shared__ float As[BK][BM + 4];
    __shared__ float Bs[BK][BN];
    const int tid = threadIdx.x;
    const int bm = blockIdx.y * BM;
    const int bn = blockIdx.x * BN;
    const int arow = tid >> 1, akq = (tid & 1) << 2;
    const int bkr = tid >> 5, bnq = (tid & 31) << 2;
    const int tx = tid & 15, ty = tid >> 4;

    const int c = bn + bnq;
    const float* bsrc = hp + (c >> 6) * (Dm * Em) + bkr * Em + (c & 63);
    const float* asrc = x + (size_t)(bm + arow) * Dm + akq;

    float acc[8][8];
#pragma unroll
    for (int i = 0; i < 8; i++)
#pragma unroll
        for (int j = 0; j < 8; j++) acc[i][j] = 0.0f;

    for (int k0 = 0; k0 < Dm; k0 += BK) {
        float4 av = *(const float4*)(asrc + k0);
        float4 bv = *(const float4*)(bsrc + (size_t)k0 * Em);
        As[akq + 0][arow] = av.x;
        As[akq + 1][arow] = av.y;
        As[akq + 2][arow] = av.z;
        As[akq + 3][arow] = av.w;
        *(float4*)&Bs[bkr][bnq] = bv;
        __syncthreads();
        float ar[8], br[8];
#pragma unroll
        for (int k = 0; k < BK; k++) {
            *(float4*)&ar[0] = *(const float4*)&As[k][ty * 4];
            *(float4*)&ar[4] = *(const float4*)&As[k][64 + ty * 4];
            *(float4*)&br[0] = *(const float4*)&Bs[k][tx * 4];
            *(float4*)&br[4] = *(const float4*)&Bs[k][64 + tx * 4];
#pragma unroll
            for (int i = 0; i < 8; i++)
#pragma unroll
                for (int j = 0; j < 8; j++)
                    acc[i][j] = fmaf(ar[i], br[j], acc[i][j]);
        }
        __syncthreads();
    }
#pragma unroll
    for (int i = 0; i < 8; i++) {
        int m = bm + ((i < 4) ? (ty * 4 + i) : (64 + ty * 4 + i - 4));
        float* dst = g_logits + (size_t)m * NC + bn;
        *(float4*)(dst + tx * 4)      = make_float4(acc[i][0], acc[i][1], acc[i][2], acc[i][3]);
        *(float4*)(dst + 64 + tx * 4) = make_float4(acc[i][4], acc[i][5], acc[i][6], acc[i][7]);
    }
}

__global__ void route_top2() {
    int t = (blockIdx.x * blockDim.x + threadIdx.x) >> 5;
    int lane = threadIdx.x & 31;
    if (t >= T_TOK) return;
    const float* lg = g_logits + (size_t)t * NC;
    float sc[Hh]; int cd[Hh];
#pragma unroll
    for (int h = 0; h < Hh; h++) {
        float v0 = lg[h * 64 + lane];
        float v1 = lg[h * 64 + 32 + lane];
        float v = v0; int idx = lane;
        if (v1 > v) { v = v1; idx = lane + 32; }
#pragma unroll
        for (int off = 16; off > 0; off >>= 1) {
            float ov = __shfl_xor_sync(0xffffffffu, v, off);
            int   oi = __shfl_xor_sync(0xffffffffu, idx, off);
            if (ov > v || (ov == v && oi < idx)) { v = ov; idx = oi; }
        }
        sc[h] = v; cd[h] = idx;
    }
    if (lane == 0) {
        int h1 = 0;
#pragma unroll
        for (int h = 1; h < Hh; h++) if (sc[h] > sc[h1]) h1 = h;
        int h2 = -1;
#pragma unroll
        for (int h = 0; h < Hh; h++) {
            if (h == h1) continue;
            if (h2 < 0 || sc[h] > sc[h2]) h2 = h;
        }
        g_sel[t * 2 + 0] = cd[h1];
        g_sel[t * 2 + 1] = cd[h2];
    }
}

__global__ void dispatch_kernel() {
    int s = blockIdx.x * 256 + threadIdx.x;
    if (s >= NSLOT) return;
    int e = g_sel[s];
    int p = atomicAdd(&g_count[e], 1);
    if (p < CAP) g_toklist[e * CAP + p] = s;
}

// ------------------------------------------------- mma.sync grouped GEMM
// A: fp32 tokens -> pre-split hi/lo bf16 smem.  B: W fp32 staged to smem as
// fp32 [k][n]; hi/lo bf16 split happens at fragment-load time (no W scratch
// arrays, no conversion pass).
// F1: g_hbuf[slot] = gelu( x[slot>>1] @ W1[e] )   K=512,  N=2048, W1=[E][D][F]
// F2: g_ybuf[slot] =        g_hbuf[slot] @ W2[e]  K=2048, N=512,  W2=[E][F][D]
template <bool F1>
__global__ __launch_bounds__(256, 1)
void moe_mma(const float* __restrict__ x, const float* __restrict__ W) {
    const int KTOT = F1 ? Dm : Fm;
    const int NTOT = F1 ? Fm : Dm;
    const int NKC  = KTOT / KCH;

    const int e = blockIdx.z;
    const int n_e = min(g_count[e], CAP);
    const int m0 = blockIdx.y * 128;
    if (m0 >= n_e) return;
    const int bn = blockIdx.x * 128;

    __shared__ __align__(16) __nv_bfloat16 sAh[128 * SPAD];
    __shared__ __align__(16) __nv_bfloat16 sAl[128 * SPAD];
    __shared__ __align__(16) float sB[KCH * BNPAD];
    __shared__ int stok[128];

    const int tid  = threadIdx.x;
    const int wid  = tid >> 5;
    const int lane = tid & 31;
    const int wm   = wid & 1;       // warp M index (2)
    const int wn   = wid >> 1;      // warp N index (4)
    const int g    = lane >> 2;
    const int t2   = (lane & 3) * 2;

    if (tid < 128) {
        int r = m0 + tid;
        stok[tid] = (r < n_e) ? g_toklist[e * CAP + r] : 0;
    }
    __syncthreads();

    // A producer: row 'arow', k-half 'ahalf' (16 floats)
    const int arow  = tid & 127;
    const int ahalf = tid >> 7;
    const int aslot = stok[arow];
    const float* arp = (F1 ? (x + (size_t)(aslot >> 1) * Dm)
                           : (g_hbuf + (size_t)aslot * Fm)) + ahalf * 16;

    // B producer: k-row kr (0..31), 4 float4 at n = nq + 32*jj
    const int kr = tid >> 3;
    const int nq = (tid & 7) * 4;
    const float* wrp = W + (size_t)e * KTOT * NTOT + bn + nq;

    float4 areg[4];
    float4 wreg[4];

    auto ldg_chunk = [&](int kc) {
        const float4* ap = (const float4*)(arp + kc * KCH);
#pragma unroll
        for (int j = 0; j < 4; j++) areg[j] = ap[j];
        const float* wk = wrp + (size_t)(kc * KCH + kr) * NTOT;
#pragma unroll
        for (int j = 0; j < 4; j++)
            wreg[j] = *(const float4*)(wk + 32 * j);
    };
    auto sts_chunk = [&]() {
#pragma unroll
        for (int j = 0; j < 4; j++) {
            uint2 h, l;
            split4(areg[j], h, l);
            int col = ahalf * 16 + j * 4;
            *(uint2*)((char*)sAh + (arow * SPAD + col) * 2) = h;
            *(uint2*)((char*)sAl + (arow * SPAD + col) * 2) = l;
        }
#pragma unroll
        for (int j = 0; j < 4; j++)
            *(float4*)&sB[kr * BNPAD + nq + 32 * j] = wreg[j];
    };

    float acc[4][4][4];
#pragma unroll
    for (int mi = 0; mi < 4; mi++)
#pragma unroll
        for (int ni = 0; ni < 4; ni++)
#pragma unroll
            for (int q = 0; q < 4; q++) acc[mi][ni][q] = 0.0f;

    ldg_chunk(0);
    sts_chunk();
    __syncthreads();

    for (int kc = 0; kc < NKC; kc++) {
        if (kc + 1 < NKC) ldg_chunk(kc + 1);

#pragma unroll
        for (int ks = 0; ks < 2; ks++) {
            const int kb = ks * 16;
            uint32_t ah[4][4], al[4][4], bh[4][2], bl[4][2];
#pragma unroll
            for (int mi = 0; mi < 4; mi++) {
                int r = wm * 64 + mi * 16 + g;
                ah[mi][0] = lds32(sAh, r,     kb + t2);
                ah[mi][1] = lds32(sAh, r + 8, kb + t2);
                ah[mi][2] = lds32(sAh, r,     kb + t2 + 8);
                ah[mi][3] = lds32(sAh, r + 8, kb + t2 + 8);
                al[mi][0] = lds32(sAl, r,     kb + t2);
                al[mi][1] = lds32(sAl, r + 8, kb + t2);
                al[mi][2] = lds32(sAl, r,     kb + t2 + 8);
                al[mi][3] = lds32(sAl, r + 8, kb + t2 + 8);
            }
#pragma unroll
            for (int ni = 0; ni < 4; ni++) {
                int rn = wn * 32 + ni * 8 + g;
#pragma unroll
                for (int hf = 0; hf < 2; hf++) {
                    int k0 = kb + t2 + hf * 8;
                    float f0 = sB[k0 * BNPAD + rn];
                    float f1 = sB[(k0 + 1) * BNPAD + rn];
                    uint32_t u0 = __float_as_uint(f0);
                    uint32_t u1 = __float_as_uint(f1);
                    bh[ni][hf] = __byte_perm(u0, u1, 0x7632);   // {hi(f0), hi(f1)}
                    float h0 = __uint_as_float(u0 & 0xFFFF0000u);
                    float h1 = __uint_as_float(u1 & 0xFFFF0000u);
                    bl[ni][hf] = cvt2_bf16(f0 - h0, f1 - h1);   // {lo(f0), lo(f1)}
                }
            }
#pragma unroll
            for (int mi = 0; mi < 4; mi++)
#pragma unroll
                for (int ni = 0; ni < 4; ni++) {
                    float* d = acc[mi][ni];
                    mma_bf16(d[0], d[1], d[2], d[3],
                             ah[mi][0], ah[mi][1], ah[mi][2], ah[mi][3],
                             bh[ni][0], bh[ni][1]);
                    mma_bf16(d[0], d[1], d[2], d[3],
                             ah[mi][0], ah[mi][1], ah[mi][2], ah[mi][3],
                             bl[ni][0], bl[ni][1]);
                    mma_bf16(d[0], d[1], d[2], d[3],
                             al[mi][0], al[mi][1], al[mi][2], al[mi][3],
                             bh[ni][0], bh[ni][1]);
                }
        }
        __syncthreads();
        if (kc + 1 < NKC) {
            sts_chunk();
            __syncthreads();
        }
    }

    // epilogue
#pragma unroll
    for (int mi = 0; mi < 4; mi++) {
#pragma unroll
        for (int half = 0; half < 2; half++) {
            int lr = wm * 64 + mi * 16 + g + half * 8;
            if (m0 + lr >= n_e) continue;
            int slot = stok[lr];
            float* orow = F1 ? (g_hbuf + (size_t)slot * Fm)
                             : (g_ybuf + (size_t)slot * Dm);
#pragma unroll
            for (int ni = 0; ni < 4; ni++) {
                int col = bn + wn * 32 + ni * 8 + t2;
                float v0 = acc[mi][ni][half * 2 + 0];
                float v1 = acc[mi][ni][half * 2 + 1];
                if (F1) { v0 = gelu_exact(v0); v1 = gelu_exact(v1); }
                *(float2*)(orow + col) = make_float2(v0, v1);
            }
        }
    }
}

// ---------------------------------------------------------------- combine
__global__ void combine_kernel(float* __restrict__ out) {
    int i = blockIdx.x * 256 + threadIdx.x;     // float4 index
    if (i >= T_TOK * Dm / 4) return;
    int t = i >> 7;
    int c = i & 127;
    const float4* y = (const float4*)g_ybuf;
    float4 a = y[(size_t)(2 * t) * 128 + c];
    float4 b = y[(size_t)(2 * t + 1) * 128 + c];
    ((float4*)out)[i] = make_float4(0.5f * (a.x + b.x), 0.5f * (a.y + b.y),
                                    0.5f * (a.z + b.z), 0.5f * (a.w + b.w));
}

// ---------------------------------------------------------------- launcher
extern "C" void kernel_launch(void* const* d_in, const int* in_sizes, int n_in,
                              void* d_out, int out_size) {
    const float* x  = (const float*)d_in[0];
    const float* hp = (const float*)d_in[1];
    const float* W1 = (const float*)d_in[2];
    const float* W2 = (const float*)d_in[3];
    float* out = (float*)d_out;

    zc_kernel<<<1, 64>>>();
    route_gemm<<<dim3(NC / BN, T_TOK / BM), 256>>>(x, hp);
    route_top2<<<(T_TOK * 32) / 256, 256>>>();
    dispatch_kernel<<<(NSLOT + 255) / 256, 256>>>();
    moe_mma<true><<<dim3(Fm / 128, CAP / 128, Em), 256>>>(x, W1);
    moe_mma<false><<<dim3(Dm / 128, CAP / 128, Em), 256>>>(nullptr, W2);
    combine_kernel<<<(T_TOK * Dm / 4 + 255) / 256, 256>>>(out);
}

// round 9
// speedup vs baseline: 1.8417x; 1.0149x over previous
#include <cuda_runtime.h>
#include <cuda_bf16.h>
#include <math.h>
#include <stdint.h>

// ---------------------------------------------------------------- constants
#define T_TOK 8192
#define Dm    512
#define Fm    2048
#define Em    64
#define Hh    4
#define NC    256
#define CAP   1024
#define NSLOT (T_TOK * 2)

// routing fp32 GEMM tiling
#define BM 128
#define BN 128
#define BK 8

// mma FFN tiling: CTA 128m x 128n, K-chunk 16, double-buffered
#define KCH   16
#define SPAD  24     // A smem row stride (bf16): 16 k + 8 pad
#define BNP   136    // B smem row stride (bf16): 128 n + 8 pad

// ---------------------------------------------------------------- scratch (~176MB, proven scale)
__device__ __align__(256) float g_logits[(size_t)T_TOK * NC];
__device__ __align__(256) int   g_sel[NSLOT];
__device__ __align__(256) int   g_count[Em];
__device__ __align__(256) int   g_toklist[Em * CAP];
__device__ __align__(256) float g_hbuf[(size_t)NSLOT * Fm];
__device__ __align__(256) float g_ybuf[(size_t)NSLOT * Dm];

// ---------------------------------------------------------------- helpers
__device__ __forceinline__ float gelu_exact(float v) {
    return 0.5f * v * (1.0f + erff(v * 0.7071067811865475f));
}
__device__ __forceinline__ uint32_t pack_bf(unsigned short a, unsigned short b) {
    return (uint32_t)a | ((uint32_t)b << 16);
}
__device__ __forceinline__ void split4(float4 v, uint2& h, uint2& l) {
    float f[4] = {v.x, v.y, v.z, v.w};
    unsigned short hs[4], ls[4];
#pragma unroll
    for (int i = 0; i < 4; i++) {
        __nv_bfloat16 hb = __float2bfloat16(f[i]);
        float r = f[i] - __bfloat162float(hb);
        hs[i] = __bfloat16_as_ushort(hb);
        ls[i] = __bfloat16_as_ushort(__float2bfloat16(r));
    }
    h = make_uint2(pack_bf(hs[0], hs[1]), pack_bf(hs[2], hs[3]));
    l = make_uint2(pack_bf(ls[0], ls[1]), pack_bf(ls[2], ls[3]));
}
__device__ __forceinline__ void mma_bf16(float& d0, float& d1, float& d2, float& d3,
                                         uint32_t a0, uint32_t a1, uint32_t a2, uint32_t a3,
                                         uint32_t b0, uint32_t b1) {
    asm volatile(
        "mma.sync.aligned.m16n8k16.row.col.f32.bf16.bf16.f32 "
        "{%0,%1,%2,%3},{%4,%5,%6,%7},{%8,%9},{%0,%1,%2,%3};"
        : "+f"(d0), "+f"(d1), "+f"(d2), "+f"(d3)
        : "r"(a0), "r"(a1), "r"(a2), "r"(a3), "r"(b0), "r"(b1));
}
__device__ __forceinline__ void ldsm_x4(uint32_t& r0, uint32_t& r1, uint32_t& r2, uint32_t& r3,
                                        uint32_t addr) {
    asm volatile("ldmatrix.sync.aligned.m8n8.x4.shared.b16 {%0,%1,%2,%3}, [%4];"
                 : "=r"(r0), "=r"(r1), "=r"(r2), "=r"(r3) : "r"(addr));
}
__device__ __forceinline__ void ldsm_x4_t(uint32_t& r0, uint32_t& r1, uint32_t& r2, uint32_t& r3,
                                          uint32_t addr) {
    asm volatile("ldmatrix.sync.aligned.m8n8.x4.trans.shared.b16 {%0,%1,%2,%3}, [%4];"
                 : "=r"(r0), "=r"(r1), "=r"(r2), "=r"(r3) : "r"(addr));
}

// ---------------------------------------------------------------- K0: misc
__global__ void zc_kernel() {
    if (threadIdx.x < Em) g_count[threadIdx.x] = 0;
}

// ---------------------------------------------------------------- routing (proven)
__global__ __launch_bounds__(256, 2)
void route_gemm(const float* __restrict__ x, const float* __restrict__ hp) {
    __shared__ float As[BK][BM + 4];
    __shared__ float Bs[BK][BN];
    const int tid = threadIdx.x;
    const int bm = blockIdx.y * BM;
    const int bn = blockIdx.x * BN;
    const int arow = tid >> 1, akq = (tid & 1) << 2;
    const int bkr = tid >> 5, bnq = (tid & 31) << 2;
    const int tx = tid & 15, ty = tid >> 4;

    const int c = bn + bnq;
    const float* bsrc = hp + (c >> 6) * (Dm * Em) + bkr * Em + (c & 63);
    const float* asrc = x + (size_t)(bm + arow) * Dm + akq;

    float acc[8][8];
#pragma unroll
    for (int i = 0; i < 8; i++)
#pragma unroll
        for (int j = 0; j < 8; j++) acc[i][j] = 0.0f;

    for (int k0 = 0; k0 < Dm; k0 += BK) {
        float4 av = *(const float4*)(asrc + k0);
        float4 bv = *(const float4*)(bsrc + (size_t)k0 * Em);
        As[akq + 0][arow] = av.x;
        As[akq + 1][arow] = av.y;
        As[akq + 2][arow] = av.z;
        As[akq + 3][arow] = av.w;
        *(float4*)&Bs[bkr][bnq] = bv;
        __syncthreads();
        float ar[8], br[8];
#pragma unroll
        for (int k = 0; k < BK; k++) {
            *(float4*)&ar[0] = *(const float4*)&As[k][ty * 4];
            *(float4*)&ar[4] = *(const float4*)&As[k][64 + ty * 4];
            *(float4*)&br[0] = *(const float4*)&Bs[k][tx * 4];
            *(float4*)&br[4] = *(const float4*)&Bs[k][64 + tx * 4];
#pragma unroll
            for (int i = 0; i < 8; i++)
#pragma unroll
                for (int j = 0; j < 8; j++)
                    acc[i][j] = fmaf(ar[i], br[j], acc[i][j]);
        }
        __syncthreads();
    }
#pragma unroll
    for (int i = 0; i < 8; i++) {
        int m = bm + ((i < 4) ? (ty * 4 + i) : (64 + ty * 4 + i - 4));
        float* dst = g_logits + (size_t)m * NC + bn;
        *(float4*)(dst + tx * 4)      = make_float4(acc[i][0], acc[i][1], acc[i][2], acc[i][3]);
        *(float4*)(dst + 64 + tx * 4) = make_float4(acc[i][4], acc[i][5], acc[i][6], acc[i][7]);
    }
}

__global__ void route_top2() {
    int t = (blockIdx.x * blockDim.x + threadIdx.x) >> 5;
    int lane = threadIdx.x & 31;
    if (t >= T_TOK) return;
    const float* lg = g_logits + (size_t)t * NC;
    float sc[Hh]; int cd[Hh];
#pragma unroll
    for (int h = 0; h < Hh; h++) {
        float v0 = lg[h * 64 + lane];
        float v1 = lg[h * 64 + 32 + lane];
        float v = v0; int idx = lane;
        if (v1 > v) { v = v1; idx = lane + 32; }
#pragma unroll
        for (int off = 16; off > 0; off >>= 1) {
            float ov = __shfl_xor_sync(0xffffffffu, v, off);
            int   oi = __shfl_xor_sync(0xffffffffu, idx, off);
            if (ov > v || (ov == v && oi < idx)) { v = ov; idx = oi; }
        }
        sc[h] = v; cd[h] = idx;
    }
    if (lane == 0) {
        int h1 = 0;
#pragma unroll
        for (int h = 1; h < Hh; h++) if (sc[h] > sc[h1]) h1 = h;
        int h2 = -1;
#pragma unroll
        for (int h = 0; h < Hh; h++) {
            if (h == h1) continue;
            if (h2 < 0 || sc[h] > sc[h2]) h2 = h;
        }
        g_sel[t * 2 + 0] = cd[h1];
        g_sel[t * 2 + 1] = cd[h2];
    }
}

__global__ void dispatch_kernel() {
    int s = blockIdx.x * 256 + threadIdx.x;
    if (s >= NSLOT) return;
    int e = g_sel[s];
    int p = atomicAdd(&g_count[e], 1);
    if (p < CAP) g_toklist[e * CAP + p] = s;
}

// ------------------------------------------------- mma.sync grouped GEMM
// A: fp32 -> hi/lo bf16 smem [row][k], ldmatrix.x4 (non-trans).
// B: W fp32 [k][n] -> hi/lo bf16 smem [k][n], ldmatrix.x4.trans.
// Double-buffered, KC=16, one __syncthreads per chunk, static smem ~42.5KB.
template <bool F1>
__global__ __launch_bounds__(256, 1)
void moe_mma(const float* __restrict__ x, const float* __restrict__ W) {
    const int KTOT = F1 ? Dm : Fm;
    const int NTOT = F1 ? Fm : Dm;
    const int NKC  = KTOT / KCH;

    const int e = blockIdx.z;
    const int n_e = min(g_count[e], CAP);
    const int m0 = blockIdx.y * 128;
    if (m0 >= n_e) return;
    const int bn = blockIdx.x * 128;

    __shared__ __align__(16) __nv_bfloat16 sAh[2][128 * SPAD];
    __shared__ __align__(16) __nv_bfloat16 sAl[2][128 * SPAD];
    __shared__ __align__(16) __nv_bfloat16 sBh[2][KCH * BNP];
    __shared__ __align__(16) __nv_bfloat16 sBl[2][KCH * BNP];
    __shared__ int stok[128];

    const int tid  = threadIdx.x;
    const int wid  = tid >> 5;
    const int lane = tid & 31;
    const int wm   = wid & 1;       // warp M index (2)
    const int wn   = wid >> 1;      // warp N index (4)
    const int g    = lane >> 2;
    const int t2   = (lane & 3) * 2;

    if (tid < 128) {
        int r = m0 + tid;
        stok[tid] = (r < n_e) ? g_toklist[e * CAP + r] : 0;
    }
    __syncthreads();

    // ---- producer mappings
    // A: row arow (0..127), k-half ahalf (8 floats each)
    const int arow  = tid >> 1;
    const int ahalf = tid & 1;
    const int aslot = stok[arow];
    const float* arp = (F1 ? (x + (size_t)(aslot >> 1) * Dm)
                           : (g_hbuf + (size_t)aslot * Fm)) + ahalf * 8;
    // B: k-row kr (0..15), n-quad nq (8 floats)
    const int kr = tid >> 4;
    const int nq = (tid & 15) * 8;
    const float* wrp = W + (size_t)e * KTOT * NTOT + (size_t)kr * NTOT + bn + nq;

    float4 areg[2];
    float4 wreg[2];
    auto ldg_chunk = [&](int kc) {
        const float4* ap = (const float4*)(arp + kc * KCH);
        areg[0] = ap[0];
        areg[1] = ap[1];
        const float* wk = wrp + (size_t)kc * KCH * NTOT;
        wreg[0] = *(const float4*)(wk);
        wreg[1] = *(const float4*)(wk + 4);
    };
    auto sts_chunk = [&](int s) {
        uint2 h0, l0, h1, l1;
        split4(areg[0], h0, l0);
        split4(areg[1], h1, l1);
        int acol = ahalf * 8;
        char* pah = (char*)sAh[s] + (arow * SPAD + acol) * 2;
        char* pal = (char*)sAl[s] + (arow * SPAD + acol) * 2;
        *(uint2*)(pah)     = h0;
        *(uint2*)(pah + 8) = h1;
        *(uint2*)(pal)     = l0;
        *(uint2*)(pal + 8) = l1;
        split4(wreg[0], h0, l0);
        split4(wreg[1], h1, l1);
        *(uint4*)((char*)sBh[s] + (kr * BNP + nq) * 2) = make_uint4(h0.x, h0.y, h1.x, h1.y);
        *(uint4*)((char*)sBl[s] + (kr * BNP + nq) * 2) = make_uint4(l0.x, l0.y, l1.x, l1.y);
    };

    // ---- consumer ldmatrix addresses (per-thread lane addressing)
    // A x4: matrices = (rows 0-7,k0-7),(rows 8-15,k0-7),(rows 0-7,k8-15),(rows 8-15,k8-15)
    const int a_r = lane & 15;          // row within 16-row tile
    const int a_c = (lane >> 4) * 8;    // k-half
    // B x4.trans: m = lane>>3: (ni_off 0,kh0),(ni_off 0,kh1),(ni_off 1,kh0),(ni_off 1,kh1)
    const int b_m  = lane >> 3;
    const int b_kr = (b_m & 1) * 8 + (lane & 7);
    const int b_n0 = wn * 32 + (b_m >> 1) * 8;   // + npair*16

    float acc[4][4][4];
#pragma unroll
    for (int mi = 0; mi < 4; mi++)
#pragma unroll
        for (int ni = 0; ni < 4; ni++)
#pragma unroll
            for (int q = 0; q < 4; q++) acc[mi][ni][q] = 0.0f;

    ldg_chunk(0);

    for (int kc = 0; kc < NKC; kc++) {
        const int cur = kc & 1;
        sts_chunk(cur);
        if (kc + 1 < NKC) ldg_chunk(kc + 1);
        __syncthreads();

        uint32_t ah[4][4], al[4][4], bh[4][2], bl[4][2];
        uint32_t baseAh = (uint32_t)__cvta_generic_to_shared(sAh[cur]);
        uint32_t baseAl = (uint32_t)__cvta_generic_to_shared(sAl[cur]);
        uint32_t baseBh = (uint32_t)__cvta_generic_to_shared(sBh[cur]);
        uint32_t baseBl = (uint32_t)__cvta_generic_to_shared(sBl[cur]);
#pragma unroll
        for (int mi = 0; mi < 4; mi++) {
            uint32_t off = ((wm * 64 + mi * 16 + a_r) * SPAD + a_c) * 2;
            ldsm_x4(ah[mi][0], ah[mi][1], ah[mi][2], ah[mi][3], baseAh + off);
            ldsm_x4(al[mi][0], al[mi][1], al[mi][2], al[mi][3], baseAl + off);
        }
#pragma unroll
        for (int np = 0; np < 2; np++) {
            uint32_t off = (b_kr * BNP + b_n0 + np * 16) * 2;
            ldsm_x4_t(bh[np * 2][0], bh[np * 2][1], bh[np * 2 + 1][0], bh[np * 2 + 1][1],
                      baseBh + off);
            ldsm_x4_t(bl[np * 2][0], bl[np * 2][1], bl[np * 2 + 1][0], bl[np * 2 + 1][1],
                      baseBl + off);
        }
#pragma unroll
        for (int mi = 0; mi < 4; mi++)
#pragma unroll
            for (int ni = 0; ni < 4; ni++) {
                float* d = acc[mi][ni];
                mma_bf16(d[0], d[1], d[2], d[3],
                         ah[mi][0], ah[mi][1], ah[mi][2], ah[mi][3],
                         bh[ni][0], bh[ni][1]);
                mma_bf16(d[0], d[1], d[2], d[3],
                         ah[mi][0], ah[mi][1], ah[mi][2], ah[mi][3],
                         bl[ni][0], bl[ni][1]);
                mma_bf16(d[0], d[1], d[2], d[3],
                         al[mi][0], al[mi][1], al[mi][2], al[mi][3],
                         bh[ni][0], bh[ni][1]);
            }
        // NOTE: no sync here; next iteration's sts targets the *other* buffer,
        // and its readers all passed this iteration's __syncthreads.
    }

    // epilogue (layout identical to R8, proven)
#pragma unroll
    for (int mi = 0; mi < 4; mi++) {
#pragma unroll
        for (int half = 0; half < 2; half++) {
            int lr = wm * 64 + mi * 16 + g + half * 8;
            if (m0 + lr >= n_e) continue;
            int slot = stok[lr];
            float* orow = F1 ? (g_hbuf + (size_t)slot * Fm)
                             : (g_ybuf + (size_t)slot * Dm);
#pragma unroll
            for (int ni = 0; ni < 4; ni++) {
                int col = bn + wn * 32 + ni * 8 + t2;
                float v0 = acc[mi][ni][half * 2 + 0];
                float v1 = acc[mi][ni][half * 2 + 1];
                if (F1) { v0 = gelu_exact(v0); v1 = gelu_exact(v1); }
                *(float2*)(orow + col) = make_float2(v0, v1);
            }
        }
    }
}

// ---------------------------------------------------------------- combine
__global__ void combine_kernel(float* __restrict__ out) {
    int i = blockIdx.x * 256 + threadIdx.x;     // float4 index
    if (i >= T_TOK * Dm / 4) return;
    int t = i >> 7;
    int c = i & 127;
    const float4* y = (const float4*)g_ybuf;
    float4 a = y[(size_t)(2 * t) * 128 + c];
    float4 b = y[(size_t)(2 * t + 1) * 128 + c];
    ((float4*)out)[i] = make_float4(0.5f * (a.x + b.x), 0.5f * (a.y + b.y),
                                    0.5f * (a.z + b.z), 0.5f * (a.w + b.w));
}

// ---------------------------------------------------------------- launcher
extern "C" void kernel_launch(void* const* d_in, const int* in_sizes, int n_in,
                              void* d_out, int out_size) {
    const float* x  = (const float*)d_in[0];
    const float* hp = (const float*)d_in[1];
    const float* W1 = (const float*)d_in[2];
    const float* W2 = (const float*)d_in[3];
    float* out = (float*)d_out;

    zc_kernel<<<1, 64>>>();
    route_gemm<<<dim3(NC / BN, T_TOK / BM), 256>>>(x, hp);
    route_top2<<<(T_TOK * 32) / 256, 256>>>();
    dispatch_kernel<<<(NSLOT + 255) / 256, 256>>>();
    moe_mma<true><<<dim3(Fm / 128, CAP / 128, Em), 256>>>(x, W1);
    moe_mma<false><<<dim3(Dm / 128, CAP / 128, Em), 256>>>(nullptr, W2);
    combine_kernel<<<(T_TOK * Dm / 4 + 255) / 256, 256>>>(out);
}

// round 10
// speedup vs baseline: 1.9686x; 1.0689x over previous
#include <cuda_runtime.h>
#include <cuda_bf16.h>
#include <math.h>
#include <stdint.h>

// ---------------------------------------------------------------- constants
#define T_TOK 8192
#define Dm    512
#define Fm    2048
#define Em    64
#define Hh    4
#define NC    256
#define CAP   1024
#define NSLOT (T_TOK * 2)

// routing fp32 GEMM tiling
#define BM 128
#define BN 128
#define BK 8

// mma FFN tiling: CTA 128m x 128n, K-chunk 16, double-buffered smem,
// depth-2 register prefetch
#define KCH   16
#define SPAD  24     // A smem row stride (bf16): 16 k + 8 pad
#define BNP   136    // B smem row stride (bf16): 128 n + 8 pad

// ---------------------------------------------------------------- scratch (~176MB, proven scale)
__device__ __align__(256) float g_logits[(size_t)T_TOK * NC];
__device__ __align__(256) int   g_sel[NSLOT];
__device__ __align__(256) int   g_count[Em];
__device__ __align__(256) int   g_toklist[Em * CAP];
__device__ __align__(256) float g_hbuf[(size_t)NSLOT * Fm];
__device__ __align__(256) float g_ybuf[(size_t)NSLOT * Dm];

// ---------------------------------------------------------------- helpers
__device__ __forceinline__ float gelu_exact(float v) {
    return 0.5f * v * (1.0f + erff(v * 0.7071067811865475f));
}
__device__ __forceinline__ uint32_t pack_bf(unsigned short a, unsigned short b) {
    return (uint32_t)a | ((uint32_t)b << 16);
}
__device__ __forceinline__ void split4(float4 v, uint2& h, uint2& l) {
    float f[4] = {v.x, v.y, v.z, v.w};
    unsigned short hs[4], ls[4];
#pragma unroll
    for (int i = 0; i < 4; i++) {
        __nv_bfloat16 hb = __float2bfloat16(f[i]);
        float r = f[i] - __bfloat162float(hb);
        hs[i] = __bfloat16_as_ushort(hb);
        ls[i] = __bfloat16_as_ushort(__float2bfloat16(r));
    }
    h = make_uint2(pack_bf(hs[0], hs[1]), pack_bf(hs[2], hs[3]));
    l = make_uint2(pack_bf(ls[0], ls[1]), pack_bf(ls[2], ls[3]));
}
__device__ __forceinline__ void mma_bf16(float& d0, float& d1, float& d2, float& d3,
                                         uint32_t a0, uint32_t a1, uint32_t a2, uint32_t a3,
                                         uint32_t b0, uint32_t b1) {
    asm volatile(
        "mma.sync.aligned.m16n8k16.row.col.f32.bf16.bf16.f32 "
        "{%0,%1,%2,%3},{%4,%5,%6,%7},{%8,%9},{%0,%1,%2,%3};"
        : "+f"(d0), "+f"(d1), "+f"(d2), "+f"(d3)
        : "r"(a0), "r"(a1), "r"(a2), "r"(a3), "r"(b0), "r"(b1));
}
__device__ __forceinline__ void ldsm_x4(uint32_t& r0, uint32_t& r1, uint32_t& r2, uint32_t& r3,
                                        uint32_t addr) {
    asm volatile("ldmatrix.sync.aligned.m8n8.x4.shared.b16 {%0,%1,%2,%3}, [%4];"
                 : "=r"(r0), "=r"(r1), "=r"(r2), "=r"(r3) : "r"(addr));
}
__device__ __forceinline__ void ldsm_x4_t(uint32_t& r0, uint32_t& r1, uint32_t& r2, uint32_t& r3,
                                          uint32_t addr) {
    asm volatile("ldmatrix.sync.aligned.m8n8.x4.trans.shared.b16 {%0,%1,%2,%3}, [%4];"
                 : "=r"(r0), "=r"(r1), "=r"(r2), "=r"(r3) : "r"(addr));
}

// ---------------------------------------------------------------- K0: misc
__global__ void zc_kernel() {
    if (threadIdx.x < Em) g_count[threadIdx.x] = 0;
}

// ---------------------------------------------------------------- routing (proven)
__global__ __launch_bounds__(256, 2)
void route_gemm(const float* __restrict__ x, const float* __restrict__ hp) {
    __shared__ float As[BK][BM + 4];
    __shared__ float Bs[BK][BN];
    const int tid = threadIdx.x;
    const int bm = blockIdx.y * BM;
    const int bn = blockIdx.x * BN;
    const int arow = tid >> 1, akq = (tid & 1) << 2;
    const int bkr = tid >> 5, bnq = (tid & 31) << 2;
    const int tx = tid & 15, ty = tid >> 4;

    const int c = bn + bnq;
    const float* bsrc = hp + (c >> 6) * (Dm * Em) + bkr * Em + (c & 63);
    const float* asrc = x + (size_t)(bm + arow) * Dm + akq;

    float acc[8][8];
#pragma unroll
    for (int i = 0; i < 8; i++)
#pragma unroll
        for (int j = 0; j < 8; j++) acc[i][j] = 0.0f;

    for (int k0 = 0; k0 < Dm; k0 += BK) {
        float4 av = *(const float4*)(asrc + k0);
        float4 bv = *(const float4*)(bsrc + (size_t)k0 * Em);
        As[akq + 0][arow] = av.x;
        As[akq + 1][arow] = av.y;
        As[akq + 2][arow] = av.z;
        As[akq + 3][arow] = av.w;
        *(float4*)&Bs[bkr][bnq] = bv;
        __syncthreads();
        float ar[8], br[8];
#pragma unroll
        for (int k = 0; k < BK; k++) {
            *(float4*)&ar[0] = *(const float4*)&As[k][ty * 4];
            *(float4*)&ar[4] = *(const float4*)&As[k][64 + ty * 4];
            *(float4*)&br[0] = *(const float4*)&Bs[k][tx * 4];
            *(float4*)&br[4] = *(const float4*)&Bs[k][64 + tx * 4];
#pragma unroll
            for (int i = 0; i < 8; i++)
#pragma unroll
                for (int j = 0; j < 8; j++)
                    acc[i][j] = fmaf(ar[i], br[j], acc[i][j]);
        }
        __syncthreads();
    }
#pragma unroll
    for (int i = 0; i < 8; i++) {
        int m = bm + ((i < 4) ? (ty * 4 + i) : (64 + ty * 4 + i - 4));
        float* dst = g_logits + (size_t)m * NC + bn;
        *(float4*)(dst + tx * 4)      = make_float4(acc[i][0], acc[i][1], acc[i][2], acc[i][3]);
        *(float4*)(dst + 64 + tx * 4) = make_float4(acc[i][4], acc[i][5], acc[i][6], acc[i][7]);
    }
}

// fused top-2 routing + dispatch (lane 0 performs the atomic dispatch inline)
__global__ void route_top2_dispatch() {
    int t = (blockIdx.x * blockDim.x + threadIdx.x) >> 5;
    int lane = threadIdx.x & 31;
    if (t >= T_TOK) return;
    const float* lg = g_logits + (size_t)t * NC;
    float sc[Hh]; int cd[Hh];
#pragma unroll
    for (int h = 0; h < Hh; h++) {
        float v0 = lg[h * 64 + lane];
        float v1 = lg[h * 64 + 32 + lane];
        float v = v0; int idx = lane;
        if (v1 > v) { v = v1; idx = lane + 32; }
#pragma unroll
        for (int off = 16; off > 0; off >>= 1) {
            float ov = __shfl_xor_sync(0xffffffffu, v, off);
            int   oi = __shfl_xor_sync(0xffffffffu, idx, off);
            if (ov > v || (ov == v && oi < idx)) { v = ov; idx = oi; }
        }
        sc[h] = v; cd[h] = idx;
    }
    if (lane == 0) {
        int h1 = 0;
#pragma unroll
        for (int h = 1; h < Hh; h++) if (sc[h] > sc[h1]) h1 = h;
        int h2 = -1;
#pragma unroll
        for (int h = 0; h < Hh; h++) {
            if (h == h1) continue;
            if (h2 < 0 || sc[h] > sc[h2]) h2 = h;
        }
        int e0 = cd[h1], e1 = cd[h2];
        int p0 = atomicAdd(&g_count[e0], 1);
        if (p0 < CAP) g_toklist[e0 * CAP + p0] = t * 2;
        int p1 = atomicAdd(&g_count[e1], 1);
        if (p1 < CAP) g_toklist[e1 * CAP + p1] = t * 2 + 1;
    }
}

// ------------------------------------------------- mma.sync grouped GEMM
// A: fp32 -> hi/lo bf16 smem [row][k], ldmatrix.x4.  B: W fp32 [k][n] ->
// hi/lo bf16 smem [k][n], ldmatrix.x4.trans.  Double-buffered smem,
// depth-2 register prefetch (STS consumes data loaded 2 chunks earlier).
template <bool F1>
__global__ __launch_bounds__(256, 1)
void moe_mma(const float* __restrict__ x, const float* __restrict__ W) {
    const int KTOT = F1 ? Dm : Fm;
    const int NTOT = F1 ? Fm : Dm;
    const int NKC  = KTOT / KCH;   // 32 (F1) / 128 (F2), both even

    const int e = blockIdx.z;
    const int n_e = min(g_count[e], CAP);
    const int m0 = blockIdx.y * 128;
    if (m0 >= n_e) return;
    const int bn = blockIdx.x * 128;

    __shared__ __align__(16) __nv_bfloat16 sAh[2][128 * SPAD];
    __shared__ __align__(16) __nv_bfloat16 sAl[2][128 * SPAD];
    __shared__ __align__(16) __nv_bfloat16 sBh[2][KCH * BNP];
    __shared__ __align__(16) __nv_bfloat16 sBl[2][KCH * BNP];
    __shared__ int stok[128];

    const int tid  = threadIdx.x;
    const int lane = tid & 31;
    const int wid  = tid >> 5;
    const int wm   = wid & 1;
    const int wn   = wid >> 1;
    const int g    = lane >> 2;
    const int t2   = (lane & 3) * 2;

    if (tid < 128) {
        int r = m0 + tid;
        stok[tid] = (r < n_e) ? g_toklist[e * CAP + r] : 0;
    }
    __syncthreads();

    // producers
    const int arow  = tid >> 1;
    const int ahalf = tid & 1;
    const int aslot = stok[arow];
    const float* arp = (F1 ? (x + (size_t)(aslot >> 1) * Dm)
                           : (g_hbuf + (size_t)aslot * Fm)) + ahalf * 8;
    const int kr = tid >> 4;
    const int nq = (tid & 15) * 8;
    const float* wrp = W + (size_t)e * KTOT * NTOT + (size_t)kr * NTOT + bn + nq;

    // two register prefetch sets
    float4 areg0[2], wreg0[2], areg1[2], wreg1[2];
    auto ldg_chunk = [&](int kc, float4* ar, float4* wr) {
        const float4* ap = (const float4*)(arp + kc * KCH);
        ar[0] = ap[0];
        ar[1] = ap[1];
        const float* wk = wrp + (size_t)kc * KCH * NTOT;
        wr[0] = *(const float4*)(wk);
        wr[1] = *(const float4*)(wk + 4);
    };
    auto sts_chunk = [&](int s, const float4* ar, const float4* wr) {
        uint2 h0, l0, h1, l1;
        split4(ar[0], h0, l0);
        split4(ar[1], h1, l1);
        int acol = ahalf * 8;
        char* pah = (char*)sAh[s] + (arow * SPAD + acol) * 2;
        char* pal = (char*)sAl[s] + (arow * SPAD + acol) * 2;
        *(uint2*)(pah)     = h0;
        *(uint2*)(pah + 8) = h1;
        *(uint2*)(pal)     = l0;
        *(uint2*)(pal + 8) = l1;
        split4(wr[0], h0, l0);
        split4(wr[1], h1, l1);
        *(uint4*)((char*)sBh[s] + (kr * BNP + nq) * 2) = make_uint4(h0.x, h0.y, h1.x, h1.y);
        *(uint4*)((char*)sBl[s] + (kr * BNP + nq) * 2) = make_uint4(l0.x, l0.y, l1.x, l1.y);
    };

    // consumer ldmatrix lane addressing
    const int a_r = lane & 15;
    const int a_c = (lane >> 4) * 8;
    const int b_m  = lane >> 3;
    const int b_kr = (b_m & 1) * 8 + (lane & 7);
    const int b_n0 = wn * 32 + (b_m >> 1) * 8;

    float acc[4][4][4];
#pragma unroll
    for (int mi = 0; mi < 4; mi++)
#pragma unroll
        for (int ni = 0; ni < 4; ni++)
#pragma unroll
            for (int q = 0; q < 4; q++) acc[mi][ni][q] = 0.0f;

    auto compute = [&](int cur) {
        uint32_t ah[4][4], al[4][4], bh[4][2], bl[4][2];
        uint32_t baseAh = (uint32_t)__cvta_generic_to_shared(sAh[cur]);
        uint32_t baseAl = (uint32_t)__cvta_generic_to_shared(sAl[cur]);
        uint32_t baseBh = (uint32_t)__cvta_generic_to_shared(sBh[cur]);
        uint32_t baseBl = (uint32_t)__cvta_generic_to_shared(sBl[cur]);
#pragma unroll
        for (int mi = 0; mi < 4; mi++) {
            uint32_t off = ((wm * 64 + mi * 16 + a_r) * SPAD + a_c) * 2;
            ldsm_x4(ah[mi][0], ah[mi][1], ah[mi][2], ah[mi][3], baseAh + off);
            ldsm_x4(al[mi][0], al[mi][1], al[mi][2], al[mi][3], baseAl + off);
        }
#pragma unroll
        for (int np = 0; np < 2; np++) {
            uint32_t off = (b_kr * BNP + b_n0 + np * 16) * 2;
            ldsm_x4_t(bh[np * 2][0], bh[np * 2][1], bh[np * 2 + 1][0], bh[np * 2 + 1][1],
                      baseBh + off);
            ldsm_x4_t(bl[np * 2][0], bl[np * 2][1], bl[np * 2 + 1][0], bl[np * 2 + 1][1],
                      baseBl + off);
        }
#pragma unroll
        for (int mi = 0; mi < 4; mi++)
#pragma unroll
            for (int ni = 0; ni < 4; ni++) {
                float* d = acc[mi][ni];
                mma_bf16(d[0], d[1], d[2], d[3],
                         ah[mi][0], ah[mi][1], ah[mi][2], ah[mi][3],
                         bh[ni][0], bh[ni][1]);
                mma_bf16(d[0], d[1], d[2], d[3],
                         ah[mi][0], ah[mi][1], ah[mi][2], ah[mi][3],
                         bl[ni][0], bl[ni][1]);
                mma_bf16(d[0], d[1], d[2], d[3],
                         al[mi][0], al[mi][1], al[mi][2], al[mi][3],
                         bh[ni][0], bh[ni][1]);
            }
    };

    // depth-2 pipeline: set0 <- chunk 0, set1 <- chunk 1
    ldg_chunk(0, areg0, wreg0);
    ldg_chunk(1, areg1, wreg1);

    for (int kc = 0; kc < NKC; kc += 2) {
        // sub-iter A: buffer 0, register set 0
        sts_chunk(0, areg0, wreg0);
        if (kc + 2 < NKC) ldg_chunk(kc + 2, areg0, wreg0);
        __syncthreads();
        compute(0);
        // sub-iter B: buffer 1, register set 1
        sts_chunk(1, areg1, wreg1);
        if (kc + 3 < NKC) ldg_chunk(kc + 3, areg1, wreg1);
        __syncthreads();
        compute(1);
    }

    // epilogue (proven layout)
#pragma unroll
    for (int mi = 0; mi < 4; mi++) {
#pragma unroll
        for (int half = 0; half < 2; half++) {
            int lr = wm * 64 + mi * 16 + g + half * 8;
            if (m0 + lr >= n_e) continue;
            int slot = stok[lr];
            float* orow = F1 ? (g_hbuf + (size_t)slot * Fm)
                             : (g_ybuf + (size_t)slot * Dm);
#pragma unroll
            for (int ni = 0; ni < 4; ni++) {
                int col = bn + wn * 32 + ni * 8 + t2;
                float v0 = acc[mi][ni][half * 2 + 0];
                float v1 = acc[mi][ni][half * 2 + 1];
                if (F1) { v0 = gelu_exact(v0); v1 = gelu_exact(v1); }
                *(float2*)(orow + col) = make_float2(v0, v1);
            }
        }
    }
}

// ---------------------------------------------------------------- combine
__global__ void combine_kernel(float* __restrict__ out) {
    int i = blockIdx.x * 256 + threadIdx.x;     // float4 index
    if (i >= T_TOK * Dm / 4) return;
    int t = i >> 7;
    int c = i & 127;
    const float4* y = (const float4*)g_ybuf;
    float4 a = y[(size_t)(2 * t) * 128 + c];
    float4 b = y[(size_t)(2 * t + 1) * 128 + c];
    ((float4*)out)[i] = make_float4(0.5f * (a.x + b.x), 0.5f * (a.y + b.y),
                                    0.5f * (a.z + b.z), 0.5f * (a.w + b.w));
}

// ---------------------------------------------------------------- launcher
extern "C" void kernel_launch(void* const* d_in, const int* in_sizes, int n_in,
                              void* d_out, int out_size) {
    const float* x  = (const float*)d_in[0];
    const float* hp = (const float*)d_in[1];
    const float* W1 = (const float*)d_in[2];
    const float* W2 = (const float*)d_in[3];
    float* out = (float*)d_out;

    zc_kernel<<<1, 64>>>();
    route_gemm<<<dim3(NC / BN, T_TOK / BM), 256>>>(x, hp);
    route_top2_dispatch<<<(T_TOK * 32) / 256, 256>>>();
    moe_mma<true><<<dim3(Fm / 128, CAP / 128, Em), 256>>>(x, W1);
    moe_mma<false><<<dim3(Dm / 128, CAP / 128, Em), 256>>>(nullptr, W2);
    combine_kernel<<<(T_TOK * Dm / 4 + 255) / 256, 256>>>(out);
}

// round 11
// speedup vs baseline: 2.0720x; 1.0526x over previous
#include <cuda_runtime.h>
#include <cuda_bf16.h>
#include <math.h>
#include <stdint.h>

// ---------------------------------------------------------------- constants
#define T_TOK 8192
#define Dm    512
#define Fm    2048
#define Em    64
#define Hh    4
#define NC    256
#define CAP   1024
#define NSLOT (T_TOK * 2)

// routing fp32 GEMM tiling
#define BM 128
#define BN 128
#define BK 8

// mma FFN tiling: CTA 128m x 128n, 512 threads (4x4 warps, 32x32 warp tile),
// K-chunk 16, double-buffered smem, depth-2 register prefetch
#define KCH   16
#define SPAD  24     // A smem row stride (bf16): 16 k + 8 pad
#define BNP   136    // B smem row stride (bf16): 128 n + 8 pad

// ---------------------------------------------------------------- scratch (~176MB, proven scale)
__device__ __align__(256) float g_logits[(size_t)T_TOK * NC];
__device__ __align__(256) int   g_count[Em];
__device__ __align__(256) int   g_toklist[Em * CAP];
__device__ __align__(256) float g_hbuf[(size_t)NSLOT * Fm];
__device__ __align__(256) float g_ybuf[(size_t)NSLOT * Dm];

// ---------------------------------------------------------------- helpers
__device__ __forceinline__ float gelu_exact(float v) {
    return 0.5f * v * (1.0f + erff(v * 0.7071067811865475f));
}
__device__ __forceinline__ uint32_t pack_bf(unsigned short a, unsigned short b) {
    return (uint32_t)a | ((uint32_t)b << 16);
}
__device__ __forceinline__ void split4(float4 v, uint2& h, uint2& l) {
    float f[4] = {v.x, v.y, v.z, v.w};
    unsigned short hs[4], ls[4];
#pragma unroll
    for (int i = 0; i < 4; i++) {
        __nv_bfloat16 hb = __float2bfloat16(f[i]);
        float r = f[i] - __bfloat162float(hb);
        hs[i] = __bfloat16_as_ushort(hb);
        ls[i] = __bfloat16_as_ushort(__float2bfloat16(r));
    }
    h = make_uint2(pack_bf(hs[0], hs[1]), pack_bf(hs[2], hs[3]));
    l = make_uint2(pack_bf(ls[0], ls[1]), pack_bf(ls[2], ls[3]));
}
__device__ __forceinline__ void mma_bf16(float& d0, float& d1, float& d2, float& d3,
                                         uint32_t a0, uint32_t a1, uint32_t a2, uint32_t a3,
                                         uint32_t b0, uint32_t b1) {
    asm volatile(
        "mma.sync.aligned.m16n8k16.row.col.f32.bf16.bf16.f32 "
        "{%0,%1,%2,%3},{%4,%5,%6,%7},{%8,%9},{%0,%1,%2,%3};"
        : "+f"(d0), "+f"(d1), "+f"(d2), "+f"(d3)
        : "r"(a0), "r"(a1), "r"(a2), "r"(a3), "r"(b0), "r"(b1));
}
__device__ __forceinline__ void ldsm_x4(uint32_t& r0, uint32_t& r1, uint32_t& r2, uint32_t& r3,
                                        uint32_t addr) {
    asm volatile("ldmatrix.sync.aligned.m8n8.x4.shared.b16 {%0,%1,%2,%3}, [%4];"
                 : "=r"(r0), "=r"(r1), "=r"(r2), "=r"(r3) : "r"(addr));
}
__device__ __forceinline__ void ldsm_x4_t(uint32_t& r0, uint32_t& r1, uint32_t& r2, uint32_t& r3,
                                          uint32_t addr) {
    asm volatile("ldmatrix.sync.aligned.m8n8.x4.trans.shared.b16 {%0,%1,%2,%3}, [%4];"
                 : "=r"(r0), "=r"(r1), "=r"(r2), "=r"(r3) : "r"(addr));
}

// ---------------------------------------------------------------- K0: misc
__global__ void zc_kernel() {
    if (threadIdx.x < Em) g_count[threadIdx.x] = 0;
}

// ---------------------------------------------------------------- routing (proven)
__global__ __launch_bounds__(256, 2)
void route_gemm(const float* __restrict__ x, const float* __restrict__ hp) {
    __shared__ float As[BK][BM + 4];
    __shared__ float Bs[BK][BN];
    const int tid = threadIdx.x;
    const int bm = blockIdx.y * BM;
    const int bn = blockIdx.x * BN;
    const int arow = tid >> 1, akq = (tid & 1) << 2;
    const int bkr = tid >> 5, bnq = (tid & 31) << 2;
    const int tx = tid & 15, ty = tid >> 4;

    const int c = bn + bnq;
    const float* bsrc = hp + (c >> 6) * (Dm * Em) + bkr * Em + (c & 63);
    const float* asrc = x + (size_t)(bm + arow) * Dm + akq;

    float acc[8][8];
#pragma unroll
    for (int i = 0; i < 8; i++)
#pragma unroll
        for (int j = 0; j < 8; j++) acc[i][j] = 0.0f;

    for (int k0 = 0; k0 < Dm; k0 += BK) {
        float4 av = *(const float4*)(asrc + k0);
        float4 bv = *(const float4*)(bsrc + (size_t)k0 * Em);
        As[akq + 0][arow] = av.x;
        As[akq + 1][arow] = av.y;
        As[akq + 2][arow] = av.z;
        As[akq + 3][arow] = av.w;
        *(float4*)&Bs[bkr][bnq] = bv;
        __syncthreads();
        float ar[8], br[8];
#pragma unroll
        for (int k = 0; k < BK; k++) {
            *(float4*)&ar[0] = *(const float4*)&As[k][ty * 4];
            *(float4*)&ar[4] = *(const float4*)&As[k][64 + ty * 4];
            *(float4*)&br[0] = *(const float4*)&Bs[k][tx * 4];
            *(float4*)&br[4] = *(const float4*)&Bs[k][64 + tx * 4];
#pragma unroll
            for (int i = 0; i < 8; i++)
#pragma unroll
                for (int j = 0; j < 8; j++)
                    acc[i][j] = fmaf(ar[i], br[j], acc[i][j]);
        }
        __syncthreads();
    }
#pragma unroll
    for (int i = 0; i < 8; i++) {
        int m = bm + ((i < 4) ? (ty * 4 + i) : (64 + ty * 4 + i - 4));
        float* dst = g_logits + (size_t)m * NC + bn;
        *(float4*)(dst + tx * 4)      = make_float4(acc[i][0], acc[i][1], acc[i][2], acc[i][3]);
        *(float4*)(dst + 64 + tx * 4) = make_float4(acc[i][4], acc[i][5], acc[i][6], acc[i][7]);
    }
}

// fused top-2 routing + dispatch
__global__ void route_top2_dispatch() {
    int t = (blockIdx.x * blockDim.x + threadIdx.x) >> 5;
    int lane = threadIdx.x & 31;
    if (t >= T_TOK) return;
    const float* lg = g_logits + (size_t)t * NC;
    float sc[Hh]; int cd[Hh];
#pragma unroll
    for (int h = 0; h < Hh; h++) {
        float v0 = lg[h * 64 + lane];
        float v1 = lg[h * 64 + 32 + lane];
        float v = v0; int idx = lane;
        if (v1 > v) { v = v1; idx = lane + 32; }
#pragma unroll
        for (int off = 16; off > 0; off >>= 1) {
            float ov = __shfl_xor_sync(0xffffffffu, v, off);
            int   oi = __shfl_xor_sync(0xffffffffu, idx, off);
            if (ov > v || (ov == v && oi < idx)) { v = ov; idx = oi; }
        }
        sc[h] = v; cd[h] = idx;
    }
    if (lane == 0) {
        int h1 = 0;
#pragma unroll
        for (int h = 1; h < Hh; h++) if (sc[h] > sc[h1]) h1 = h;
        int h2 = -1;
#pragma unroll
        for (int h = 0; h < Hh; h++) {
            if (h == h1) continue;
            if (h2 < 0 || sc[h] > sc[h2]) h2 = h;
        }
        int e0 = cd[h1], e1 = cd[h2];
        int p0 = atomicAdd(&g_count[e0], 1);
        if (p0 < CAP) g_toklist[e0 * CAP + p0] = t * 2;
        int p1 = atomicAdd(&g_count[e1], 1);
        if (p1 < CAP) g_toklist[e1 * CAP + p1] = t * 2 + 1;
    }
}

// ------------------------------------------------- mma.sync grouped GEMM
// 512 threads, warp grid 4x4, warp tile 32x32.
template <bool F1>
__global__ __launch_bounds__(512, 1)
void moe_mma(const float* __restrict__ x, const float* __restrict__ W) {
    const int KTOT = F1 ? Dm : Fm;
    const int NTOT = F1 ? Fm : Dm;
    const int NKC  = KTOT / KCH;   // 32 / 128, even

    const int e = blockIdx.z;
    const int n_e = min(g_count[e], CAP);
    const int m0 = blockIdx.y * 128;
    if (m0 >= n_e) return;
    const int bn = blockIdx.x * 128;

    __shared__ __align__(16) __nv_bfloat16 sAh[2][128 * SPAD];
    __shared__ __align__(16) __nv_bfloat16 sAl[2][128 * SPAD];
    __shared__ __align__(16) __nv_bfloat16 sBh[2][KCH * BNP];
    __shared__ __align__(16) __nv_bfloat16 sBl[2][KCH * BNP];
    __shared__ int stok[128];

    const int tid  = threadIdx.x;
    const int lane = tid & 31;
    const int wid  = tid >> 5;
    const int wm   = wid & 3;       // warp M index (4)
    const int wn   = wid >> 2;      // warp N index (4)
    const int g    = lane >> 2;
    const int t2   = (lane & 3) * 2;

    if (tid < 128) {
        int r = m0 + tid;
        stok[tid] = (r < n_e) ? g_toklist[e * CAP + r] : 0;
    }
    __syncthreads();

    // producers: A row arow (0..127), k-quad aq; B k-row kr, n-quad nq
    const int arow = tid >> 2;
    const int aq   = tid & 3;
    const int aslot = stok[arow];
    const float* arp = (F1 ? (x + (size_t)(aslot >> 1) * Dm)
                           : (g_hbuf + (size_t)aslot * Fm)) + aq * 4;
    const int kr = tid >> 5;
    const int nq = (tid & 31) * 4;
    const float* wrp = W + (size_t)e * KTOT * NTOT + (size_t)kr * NTOT + bn + nq;

    float4 areg0, wreg0, areg1, wreg1;
    auto ldg_chunk = [&](int kc, float4& ar, float4& wr) {
        ar = *(const float4*)(arp + kc * KCH);
        wr = *(const float4*)(wrp + (size_t)kc * KCH * NTOT);
    };
    auto sts_chunk = [&](int s, float4 ar, float4 wr) {
        uint2 h, l;
        split4(ar, h, l);
        *(uint2*)((char*)sAh[s] + (arow * SPAD + aq * 4) * 2) = h;
        *(uint2*)((char*)sAl[s] + (arow * SPAD + aq * 4) * 2) = l;
        split4(wr, h, l);
        *(uint2*)((char*)sBh[s] + (kr * BNP + nq) * 2) = h;
        *(uint2*)((char*)sBl[s] + (kr * BNP + nq) * 2) = l;
    };

    // consumer ldmatrix lane addressing (mappings proven in R9/R10)
    const int a_r = lane & 15;
    const int a_c = (lane >> 4) * 8;
    const int b_m  = lane >> 3;
    const int b_kr = (b_m & 1) * 8 + (lane & 7);
    const int b_n0 = wn * 32 + (b_m >> 1) * 8;

    float acc[2][4][4];
#pragma unroll
    for (int mi = 0; mi < 2; mi++)
#pragma unroll
        for (int ni = 0; ni < 4; ni++)
#pragma unroll
            for (int q = 0; q < 4; q++) acc[mi][ni][q] = 0.0f;

    auto compute = [&](int cur) {
        uint32_t ah[2][4], al[2][4], bh[4][2], bl[4][2];
        uint32_t baseAh = (uint32_t)__cvta_generic_to_shared(sAh[cur]);
        uint32_t baseAl = (uint32_t)__cvta_generic_to_shared(sAl[cur]);
        uint32_t baseBh = (uint32_t)__cvta_generic_to_shared(sBh[cur]);
        uint32_t baseBl = (uint32_t)__cvta_generic_to_shared(sBl[cur]);
#pragma unroll
        for (int mi = 0; mi < 2; mi++) {
            uint32_t off = ((wm * 32 + mi * 16 + a_r) * SPAD + a_c) * 2;
            ldsm_x4(ah[mi][0], ah[mi][1], ah[mi][2], ah[mi][3], baseAh + off);
            ldsm_x4(al[mi][0], al[mi][1], al[mi][2], al[mi][3], baseAl + off);
        }
#pragma unroll
        for (int np = 0; np < 2; np++) {
            uint32_t off = (b_kr * BNP + b_n0 + np * 16) * 2;
            ldsm_x4_t(bh[np * 2][0], bh[np * 2][1], bh[np * 2 + 1][0], bh[np * 2 + 1][1],
                      baseBh + off);
            ldsm_x4_t(bl[np * 2][0], bl[np * 2][1], bl[np * 2 + 1][0], bl[np * 2 + 1][1],
                      baseBl + off);
        }
#pragma unroll
        for (int mi = 0; mi < 2; mi++)
#pragma unroll
            for (int ni = 0; ni < 4; ni++) {
                float* d = acc[mi][ni];
                mma_bf16(d[0], d[1], d[2], d[3],
                         ah[mi][0], ah[mi][1], ah[mi][2], ah[mi][3],
                         bh[ni][0], bh[ni][1]);
                mma_bf16(d[0], d[1], d[2], d[3],
                         ah[mi][0], ah[mi][1], ah[mi][2], ah[mi][3],
                         bl[ni][0], bl[ni][1]);
                mma_bf16(d[0], d[1], d[2], d[3],
                         al[mi][0], al[mi][1], al[mi][2], al[mi][3],
                         bh[ni][0], bh[ni][1]);
            }
    };

    // depth-2 pipeline
    ldg_chunk(0, areg0, wreg0);
    ldg_chunk(1, areg1, wreg1);

    for (int kc = 0; kc < NKC; kc += 2) {
        sts_chunk(0, areg0, wreg0);
        if (kc + 2 < NKC) ldg_chunk(kc + 2, areg0, wreg0);
        __syncthreads();
        compute(0);
        sts_chunk(1, areg1, wreg1);
        if (kc + 3 < NKC) ldg_chunk(kc + 3, areg1, wreg1);
        __syncthreads();
        compute(1);
    }

    // epilogue
#pragma unroll
    for (int mi = 0; mi < 2; mi++) {
#pragma unroll
        for (int half = 0; half < 2; half++) {
            int lr = wm * 32 + mi * 16 + g + half * 8;
            if (m0 + lr >= n_e) continue;
            int slot = stok[lr];
            float* orow = F1 ? (g_hbuf + (size_t)slot * Fm)
                             : (g_ybuf + (size_t)slot * Dm);
#pragma unroll
            for (int ni = 0; ni < 4; ni++) {
                int col = bn + wn * 32 + ni * 8 + t2;
                float v0 = acc[mi][ni][half * 2 + 0];
                float v1 = acc[mi][ni][half * 2 + 1];
                if (F1) { v0 = gelu_exact(v0); v1 = gelu_exact(v1); }
                *(float2*)(orow + col) = make_float2(v0, v1);
            }
        }
    }
}

// ---------------------------------------------------------------- combine
__global__ void combine_kernel(float* __restrict__ out) {
    int i = blockIdx.x * 256 + threadIdx.x;     // float4 index
    if (i >= T_TOK * Dm / 4) return;
    int t = i >> 7;
    int c = i & 127;
    const float4* y = (const float4*)g_ybuf;
    float4 a = y[(size_t)(2 * t) * 128 + c];
    float4 b = y[(size_t)(2 * t + 1) * 128 + c];
    ((float4*)out)[i] = make_float4(0.5f * (a.x + b.x), 0.5f * (a.y + b.y),
                                    0.5f * (a.z + b.z), 0.5f * (a.w + b.w));
}

// ---------------------------------------------------------------- launcher
extern "C" void kernel_launch(void* const* d_in, const int* in_sizes, int n_in,
                              void* d_out, int out_size) {
    const float* x  = (const float*)d_in[0];
    const float* hp = (const float*)d_in[1];
    const float* W1 = (const float*)d_in[2];
    const float* W2 = (const float*)d_in[3];
    float* out = (float*)d_out;

    zc_kernel<<<1, 64>>>();
    route_gemm<<<dim3(NC / BN, T_TOK / BM), 256>>>(x, hp);
    route_top2_dispatch<<<(T_TOK * 32) / 256, 256>>>();
    moe_mma<true><<<dim3(Fm / 128, CAP / 128, Em), 512>>>(x, W1);
    moe_mma<false><<<dim3(Dm / 128, CAP / 128, Em), 512>>>(nullptr, W2);
    combine_kernel<<<(T_TOK * Dm / 4 + 255) / 256, 256>>>(out);
}

// round 12
// speedup vs baseline: 2.5695x; 1.2401x over previous
#include <cuda_runtime.h>
#include <cuda_fp16.h>
#include <math.h>
#include <stdint.h>

// ---------------------------------------------------------------- constants
#define T_TOK 8192
#define Dm    512
#define Fm    2048
#define Em    64
#define Hh    4
#define NC    256
#define CAP   1024
#define NSLOT (T_TOK * 2)

// routing fp32 GEMM tiling
#define BM 128
#define BN 128
#define BK 8

// mma FFN tiling: CTA 128m x 256n, 256 threads (2x4 warps, 64x64 warp tile),
// K-chunk 16, double-buffered smem, depth-2 register prefetch, fp16 2-term.
#define KCH   16
#define SPAD  24     // A smem row stride (fp16): 16 k + 8 pad
#define BNP2  264    // B smem row stride (fp16): 256 n + 8 pad

// ---------------------------------------------------------------- scratch
__device__ __align__(256) float g_logits[(size_t)T_TOK * NC];
__device__ __align__(256) int   g_count[Em];
__device__ __align__(256) int   g_toklist[Em * CAP];
__device__ __align__(256) float g_hbuf[(size_t)NSLOT * Fm];
__device__ __align__(256) float g_ybuf[(size_t)NSLOT * Dm];

// ---------------------------------------------------------------- helpers
__device__ __forceinline__ float gelu_exact(float v) {
    return 0.5f * v * (1.0f + erff(v * 0.7071067811865475f));
}
__device__ __forceinline__ uint32_t pack_h(__half a, __half b) {
    return (uint32_t)__half_as_ushort(a) | ((uint32_t)__half_as_ushort(b) << 16);
}
// split float4 -> 4 hi fp16 (uint2) + 4 lo fp16 (uint2)
__device__ __forceinline__ void split4h(float4 v, uint2& h, uint2& l) {
    float f[4] = {v.x, v.y, v.z, v.w};
    __half hh[4], ll[4];
#pragma unroll
    for (int i = 0; i < 4; i++) {
        hh[i] = __float2half_rn(f[i]);
        ll[i] = __float2half_rn(f[i] - __half2float(hh[i]));
    }
    h = make_uint2(pack_h(hh[0], hh[1]), pack_h(hh[2], hh[3]));
    l = make_uint2(pack_h(ll[0], ll[1]), pack_h(ll[2], ll[3]));
}
// hi-only variant for B
__device__ __forceinline__ uint2 hi4h(float4 v) {
    return make_uint2(pack_h(__float2half_rn(v.x), __float2half_rn(v.y)),
                      pack_h(__float2half_rn(v.z), __float2half_rn(v.w)));
}
__device__ __forceinline__ void mma_f16(float& d0, float& d1, float& d2, float& d3,
                                        uint32_t a0, uint32_t a1, uint32_t a2, uint32_t a3,
                                        uint32_t b0, uint32_t b1) {
    asm volatile(
        "mma.sync.aligned.m16n8k16.row.col.f32.f16.f16.f32 "
        "{%0,%1,%2,%3},{%4,%5,%6,%7},{%8,%9},{%0,%1,%2,%3};"
        : "+f"(d0), "+f"(d1), "+f"(d2), "+f"(d3)
        : "r"(a0), "r"(a1), "r"(a2), "r"(a3), "r"(b0), "r"(b1));
}
__device__ __forceinline__ void ldsm_x4(uint32_t& r0, uint32_t& r1, uint32_t& r2, uint32_t& r3,
                                        uint32_t addr) {
    asm volatile("ldmatrix.sync.aligned.m8n8.x4.shared.b16 {%0,%1,%2,%3}, [%4];"
                 : "=r"(r0), "=r"(r1), "=r"(r2), "=r"(r3) : "r"(addr));
}
__device__ __forceinline__ void ldsm_x4_t(uint32_t& r0, uint32_t& r1, uint32_t& r2, uint32_t& r3,
                                          uint32_t addr) {
    asm volatile("ldmatrix.sync.aligned.m8n8.x4.trans.shared.b16 {%0,%1,%2,%3}, [%4];"
                 : "=r"(r0), "=r"(r1), "=r"(r2), "=r"(r3) : "r"(addr));
}

// ---------------------------------------------------------------- K0: misc
__global__ void zc_kernel() {
    if (threadIdx.x < Em) g_count[threadIdx.x] = 0;
}

// ---------------------------------------------------------------- routing (proven, fp32-exact)
__global__ __launch_bounds__(256, 2)
void route_gemm(const float* __restrict__ x, const float* __restrict__ hp) {
    __shared__ float As[BK][BM + 4];
    __shared__ float Bs[BK][BN];
    const int tid = threadIdx.x;
    const int bm = blockIdx.y * BM;
    const int bn = blockIdx.x * BN;
    const int arow = tid >> 1, akq = (tid & 1) << 2;
    const int bkr = tid >> 5, bnq = (tid & 31) << 2;
    const int tx = tid & 15, ty = tid >> 4;

    const int c = bn + bnq;
    const float* bsrc = hp + (c >> 6) * (Dm * Em) + bkr * Em + (c & 63);
    const float* asrc = x + (size_t)(bm + arow) * Dm + akq;

    float acc[8][8];
#pragma unroll
    for (int i = 0; i < 8; i++)
#pragma unroll
        for (int j = 0; j < 8; j++) acc[i][j] = 0.0f;

    for (int k0 = 0; k0 < Dm; k0 += BK) {
        float4 av = *(const float4*)(asrc + k0);
        float4 bv = *(const float4*)(bsrc + (size_t)k0 * Em);
        As[akq + 0][arow] = av.x;
        As[akq + 1][arow] = av.y;
        As[akq + 2][arow] = av.z;
        As[akq + 3][arow] = av.w;
        *(float4*)&Bs[bkr][bnq] = bv;
        __syncthreads();
        float ar[8], br[8];
#pragma unroll
        for (int k = 0; k < BK; k++) {
            *(float4*)&ar[0] = *(const float4*)&As[k][ty * 4];
            *(float4*)&ar[4] = *(const float4*)&As[k][64 + ty * 4];
            *(float4*)&br[0] = *(const float4*)&Bs[k][tx * 4];
            *(float4*)&br[4] = *(const float4*)&Bs[k][64 + tx * 4];
#pragma unroll
            for (int i = 0; i < 8; i++)
#pragma unroll
                for (int j = 0; j < 8; j++)
                    acc[i][j] = fmaf(ar[i], br[j], acc[i][j]);
        }
        __syncthreads();
    }
#pragma unroll
    for (int i = 0; i < 8; i++) {
        int m = bm + ((i < 4) ? (ty * 4 + i) : (64 + ty * 4 + i - 4));
        float* dst = g_logits + (size_t)m * NC + bn;
        *(float4*)(dst + tx * 4)      = make_float4(acc[i][0], acc[i][1], acc[i][2], acc[i][3]);
        *(float4*)(dst + 64 + tx * 4) = make_float4(acc[i][4], acc[i][5], acc[i][6], acc[i][7]);
    }
}

// fused top-2 routing + dispatch
__global__ void route_top2_dispatch() {
    int t = (blockIdx.x * blockDim.x + threadIdx.x) >> 5;
    int lane = threadIdx.x & 31;
    if (t >= T_TOK) return;
    const float* lg = g_logits + (size_t)t * NC;
    float sc[Hh]; int cd[Hh];
#pragma unroll
    for (int h = 0; h < Hh; h++) {
        float v0 = lg[h * 64 + lane];
        float v1 = lg[h * 64 + 32 + lane];
        float v = v0; int idx = lane;
        if (v1 > v) { v = v1; idx = lane + 32; }
#pragma unroll
        for (int off = 16; off > 0; off >>= 1) {
            float ov = __shfl_xor_sync(0xffffffffu, v, off);
            int   oi = __shfl_xor_sync(0xffffffffu, idx, off);
            if (ov > v || (ov == v && oi < idx)) { v = ov; idx = oi; }
        }
        sc[h] = v; cd[h] = idx;
    }
    if (lane == 0) {
        int h1 = 0;
#pragma unroll
        for (int h = 1; h < Hh; h++) if (sc[h] > sc[h1]) h1 = h;
        int h2 = -1;
#pragma unroll
        for (int h = 0; h < Hh; h++) {
            if (h == h1) continue;
            if (h2 < 0 || sc[h] > sc[h2]) h2 = h;
        }
        int e0 = cd[h1], e1 = cd[h2];
        int p0 = atomicAdd(&g_count[e0], 1);
        if (p0 < CAP) g_toklist[e0 * CAP + p0] = t * 2;
        int p1 = atomicAdd(&g_count[e1], 1);
        if (p1 < CAP) g_toklist[e1 * CAP + p1] = t * 2 + 1;
    }
}

// ------------------------------------------------- mma.sync grouped GEMM
// fp16 2-term split (A = hi+lo, B = hi only). CTA 128m x 256n, 8 warps
// (warp tile 64x64), KCH=16, double-buffered smem, depth-2 reg prefetch.
template <bool F1>
__global__ __launch_bounds__(256, 1)
void moe_mma(const float* __restrict__ x, const float* __restrict__ W) {
    const int KTOT = F1 ? Dm : Fm;
    const int NTOT = F1 ? Fm : Dm;
    const int NKC  = KTOT / KCH;   // 32 / 128, even

    const int e = blockIdx.z;
    const int n_e = min(g_count[e], CAP);
    const int m0 = blockIdx.y * 128;
    if (m0 >= n_e) return;
    const int bn = blockIdx.x * 256;

    __shared__ __align__(16) __half sAh[2][128 * SPAD];
    __shared__ __align__(16) __half sAl[2][128 * SPAD];
    __shared__ __align__(16) __half sBh[2][KCH * BNP2];
    __shared__ int stok[128];

    const int tid  = threadIdx.x;
    const int lane = tid & 31;
    const int wid  = tid >> 5;
    const int wm   = wid & 1;       // warp M index (2)
    const int wn   = wid >> 1;      // warp N index (4)
    const int g    = lane >> 2;
    const int t2   = (lane & 3) * 2;

    if (tid < 128) {
        int r = m0 + tid;
        stok[tid] = (r < n_e) ? g_toklist[e * CAP + r] : 0;
    }
    __syncthreads();

    // producers: A row arow (0..127) x 8 k-floats; B k-row kr x 16 n-floats
    const int arow  = tid >> 1;
    const int ahalf = tid & 1;
    const int aslot = stok[arow];
    const float* arp = (F1 ? (x + (size_t)(aslot >> 1) * Dm)
                           : (g_hbuf + (size_t)aslot * Fm)) + ahalf * 8;
    const int kr = tid >> 4;
    const int nq = (tid & 15) * 16;
    const float* wrp = W + (size_t)e * KTOT * NTOT + (size_t)kr * NTOT + bn + nq;

    float4 areg0[2], areg1[2], wreg0[4], wreg1[4];
    auto ldg_chunk = [&](int kc, float4* ar, float4* wr) {
        const float4* ap = (const float4*)(arp + kc * KCH);
        ar[0] = ap[0];
        ar[1] = ap[1];
        const float4* wk = (const float4*)(wrp + (size_t)kc * KCH * NTOT);
#pragma unroll
        for (int j = 0; j < 4; j++) wr[j] = wk[j];
    };
    auto sts_chunk = [&](int s, const float4* ar, const float4* wr) {
        uint2 h0, l0, h1, l1;
        split4h(ar[0], h0, l0);
        split4h(ar[1], h1, l1);
        int acol = ahalf * 8;
        char* pah = (char*)sAh[s] + (arow * SPAD + acol) * 2;
        char* pal = (char*)sAl[s] + (arow * SPAD + acol) * 2;
        *(uint2*)(pah)     = h0;
        *(uint2*)(pah + 8) = h1;
        *(uint2*)(pal)     = l0;
        *(uint2*)(pal + 8) = l1;
        uint2 b0 = hi4h(wr[0]), b1 = hi4h(wr[1]), b2 = hi4h(wr[2]), b3 = hi4h(wr[3]);
        char* pb = (char*)sBh[s] + (kr * BNP2 + nq) * 2;
        *(uint4*)(pb)      = make_uint4(b0.x, b0.y, b1.x, b1.y);
        *(uint4*)(pb + 16) = make_uint4(b2.x, b2.y, b3.x, b3.y);
    };

    // consumer ldmatrix lane addressing (R9-R11 proven mappings, n widened)
    const int a_r = lane & 15;
    const int a_c = (lane >> 4) * 8;
    const int b_m  = lane >> 3;
    const int b_kr = (b_m & 1) * 8 + (lane & 7);
    const int b_n0 = wn * 64 + (b_m >> 1) * 8;

    float acc[4][8][4];
#pragma unroll
    for (int mi = 0; mi < 4; mi++)
#pragma unroll
        for (int ni = 0; ni < 8; ni++)
#pragma unroll
            for (int q = 0; q < 4; q++) acc[mi][ni][q] = 0.0f;

    auto compute = [&](int cur) {
        uint32_t ah[4][4], al[4][4], bh[8][2];
        uint32_t baseAh = (uint32_t)__cvta_generic_to_shared(sAh[cur]);
        uint32_t baseAl = (uint32_t)__cvta_generic_to_shared(sAl[cur]);
        uint32_t baseBh = (uint32_t)__cvta_generic_to_shared(sBh[cur]);
#pragma unroll
        for (int mi = 0; mi < 4; mi++) {
            uint32_t off = ((wm * 64 + mi * 16 + a_r) * SPAD + a_c) * 2;
            ldsm_x4(ah[mi][0], ah[mi][1], ah[mi][2], ah[mi][3], baseAh + off);
            ldsm_x4(al[mi][0], al[mi][1], al[mi][2], al[mi][3], baseAl + off);
        }
#pragma unroll
        for (int np = 0; np < 4; np++) {
            uint32_t off = (b_kr * BNP2 + b_n0 + np * 16) * 2;
            ldsm_x4_t(bh[np * 2][0], bh[np * 2][1], bh[np * 2 + 1][0], bh[np * 2 + 1][1],
                      baseBh + off);
        }
#pragma unroll
        for (int mi = 0; mi < 4; mi++)
#pragma unroll
            for (int ni = 0; ni < 8; ni++) {
                float* d = acc[mi][ni];
                mma_f16(d[0], d[1], d[2], d[3],
                        ah[mi][0], ah[mi][1], ah[mi][2], ah[mi][3],
                        bh[ni][0], bh[ni][1]);
                mma_f16(d[0], d[1], d[2], d[3],
                        al[mi][0], al[mi][1], al[mi][2], al[mi][3],
                        bh[ni][0], bh[ni][1]);
            }
    };

    // depth-2 pipeline
    ldg_chunk(0, areg0, wreg0);
    ldg_chunk(1, areg1, wreg1);

    for (int kc = 0; kc < NKC; kc += 2) {
        sts_chunk(0, areg0, wreg0);
        if (kc + 2 < NKC) ldg_chunk(kc + 2, areg0, wreg0);
        __syncthreads();
        compute(0);
        sts_chunk(1, areg1, wreg1);
        if (kc + 3 < NKC) ldg_chunk(kc + 3, areg1, wreg1);
        __syncthreads();
        compute(1);
    }

    // epilogue
#pragma unroll
    for (int mi = 0; mi < 4; mi++) {
#pragma unroll
        for (int half = 0; half < 2; half++) {
            int lr = wm * 64 + mi * 16 + g + half * 8;
            if (m0 + lr >= n_e) continue;
            int slot = stok[lr];
            float* orow = F1 ? (g_hbuf + (size_t)slot * Fm)
                             : (g_ybuf + (size_t)slot * Dm);
#pragma unroll
            for (int ni = 0; ni < 8; ni++) {
                int col = bn + wn * 64 + ni * 8 + t2;
                float v0 = acc[mi][ni][half * 2 + 0];
                float v1 = acc[mi][ni][half * 2 + 1];
                if (F1) { v0 = gelu_exact(v0); v1 = gelu_exact(v1); }
                *(float2*)(orow + col) = make_float2(v0, v1);
            }
        }
    }
}

// ---------------------------------------------------------------- combine
__global__ void combine_kernel(float* __restrict__ out) {
    int i = blockIdx.x * 256 + threadIdx.x;     // float4 index
    if (i >= T_TOK * Dm / 4) return;
    int t = i >> 7;
    int c = i & 127;
    const float4* y = (const float4*)g_ybuf;
    float4 a = y[(size_t)(2 * t) * 128 + c];
    float4 b = y[(size_t)(2 * t + 1) * 128 + c];
    ((float4*)out)[i] = make_float4(0.5f * (a.x + b.x), 0.5f * (a.y + b.y),
                                    0.5f * (a.z + b.z), 0.5f * (a.w + b.w));
}

// ---------------------------------------------------------------- launcher
extern "C" void kernel_launch(void* const* d_in, const int* in_sizes, int n_in,
                              void* d_out, int out_size) {
    const float* x  = (const float*)d_in[0];
    const float* hp = (const float*)d_in[1];
    const float* W1 = (const float*)d_in[2];
    const float* W2 = (const float*)d_in[3];
    float* out = (float*)d_out;

    zc_kernel<<<1, 64>>>();
    route_gemm<<<dim3(NC / BN, T_TOK / BM), 256>>>(x, hp);
    route_top2_dispatch<<<(T_TOK * 32) / 256, 256>>>();
    moe_mma<true><<<dim3(Fm / 256, CAP / 128, Em), 256>>>(x, W1);
    moe_mma<false><<<dim3(Dm / 256, CAP / 128, Em), 256>>>(nullptr, W2);
    combine_kernel<<<(T_TOK * Dm / 4 + 255) / 256, 256>>>(out);
}